// round 7
// baseline (speedup 1.0000x reference)
#include <cuda_runtime.h>

// ModuleSoftsplat forward summation splatting, tiled-gather v4.
// image [4,64,512,512] f32, flow [4,2,512,512] f32 -> out [4,64,512,512] f32.
//
// v4 changes vs v3 (which ran at 1 CTA/SM, occ 23%):
//  - bin entries packed to 4 bytes: (weight as 20-bit fixed point) << 12 | sidx
//  - KCAP 9 -> 8, slot-major bin layout (conflict-free LDS.32)
//  - smem 114.7 KB -> 73.7 KB  => 3 CTAs/SM, occ cap 75%

#define SS_B   4
#define SS_C   64
#define SS_H   512
#define SS_W   512
#define SS_HW  (SS_H * SS_W)
#define SS_CHW (SS_C * SS_HW)

#define TS     32
#define HALO   8
#define RW     (TS + 2 * HALO)        // 48
#define RN     (RW * RW)              // 2304
#define KCAP   8
#define NCELLS (TS * TS)              // 1024

#define OVF_CAP (4 * SS_B * SS_HW)    // worst case, nothing dropped

// smem: cnt 4096 + bin 32768 + img 36864 = 73728 bytes -> 3 CTAs/SM
#define SM_BIN_OFF  (NCELLS * 4)
#define SM_IMG_OFF  (SM_BIN_OFF + NCELLS * KCAP * 4)
#define SMEM_BYTES  (SM_IMG_OFF + RN * 16)

#define W_SCALE 1048576.0f            // 2^20
#define W_INV   (1.0f / 1048576.0f)

__device__ int   g_ovf_n;
__device__ int   g_ovf_cell[OVF_CAP];   // (b<<18) | (y<<9) | x
__device__ int   g_ovf_src [OVF_CAP];   // (b<<18) | spatial
__device__ float g_ovf_w   [OVF_CAP];

__device__ __forceinline__ void ovf_append(int cellp, int src, float w) {
    int slot = atomicAdd(&g_ovf_n, 1);
    if (slot < OVF_CAP) {
        g_ovf_cell[slot] = cellp;
        g_ovf_src [slot] = src;
        g_ovf_w   [slot] = w;
    }
}

__global__ void ss_reset_kernel() { g_ovf_n = 0; }

// ---------------------------------------------------------------------------
// Main tiled gather kernel. Grid: 1024 = b(2) | ty(4) | tx(4).
// ---------------------------------------------------------------------------
__global__ __launch_bounds__(256, 3) void ss_gather_kernel(
    const float* __restrict__ img,
    const float* __restrict__ flow,
    float* __restrict__ out)
{
    extern __shared__ unsigned char sraw[];
    int*      s_cnt = (int*)sraw;
    unsigned* s_bin = (unsigned*)(sraw + SM_BIN_OFF);   // slot-major: [slot][cell]
    float4*   s_img = (float4*)(sraw + SM_IMG_OFF);

    const int tid = threadIdx.x;
    const int bi  = blockIdx.x;
    const int tx0 = (bi & 15) * TS;
    const int ty0 = ((bi >> 4) & 15) * TS;
    const int b   = bi >> 8;

    for (int i = tid; i < NCELLS; i += 256) s_cnt[i] = 0;
    __syncthreads();

    // -------- Phase A: bin contributors (channel-independent, once) --------
    const float* flowb = flow + (size_t)b * 2 * SS_HW;
    #pragma unroll
    for (int it = 0; it < RN / 256; it++) {
        int i  = tid + it * 256;
        int ly = i / RW, lx = i - ly * RW;
        int gy = ty0 - HALO + ly, gx = tx0 - HALO + lx;
        if ((unsigned)gx >= SS_W || (unsigned)gy >= SS_H) continue;
        int sp = (gy << 9) + gx;
        float fx = flowb[sp]         + (float)gx;
        float fy = flowb[sp + SS_HW] + (float)gy;
        float x0f = floorf(fx), y0f = floorf(fy);
        int x0 = (int)x0f, y0 = (int)y0f;
        float wx1 = fx - x0f, wx0 = 1.0f - wx1;
        float wy1 = fy - y0f, wy0 = 1.0f - wy1;
        int sidx = ly * RW + lx;
        bool own = (gx >= tx0) && (gx < tx0 + TS) && (gy >= ty0) && (gy < ty0 + TS);
        #pragma unroll
        for (int k = 0; k < 4; k++) {
            int dx = k & 1, dy = k >> 1;
            int cx = x0 + dx, cy = y0 + dy;
            if ((unsigned)cx >= SS_W || (unsigned)cy >= SS_H) continue;
            float w = (dx ? wx1 : wx0) * (dy ? wy1 : wy0);
            int lcx = cx - tx0, lcy = cy - ty0;
            if ((unsigned)lcx < TS && (unsigned)lcy < TS) {
                int cid  = (lcy << 5) + lcx;
                int slot = atomicAdd(&s_cnt[cid], 1);
                if (slot < KCAP) {
                    unsigned wf = __float2uint_rn(w * W_SCALE);
                    if (wf > 0xFFFFFu) wf = 0xFFFFFu;
                    s_bin[slot * NCELLS + cid] = (wf << 12) | (unsigned)sidx;
                } else {
                    ovf_append((b << 18) | (cy << 9) | cx, (b << 18) | sp, w);
                }
            } else if (own) {
                int tcx = cx & ~(TS - 1), tcy = cy & ~(TS - 1);
                bool cap = (gx >= tcx - HALO) && (gx < tcx + TS + HALO) &&
                           (gy >= tcy - HALO) && (gy < tcy + TS + HALO);
                if (!cap)
                    ovf_append((b << 18) | (cy << 9) | cx, (b << 18) | sp, w);
            }
        }
    }
    __syncthreads();

    const int n0 = min(s_cnt[tid      ], KCAP);
    const int n1 = min(s_cnt[tid + 256], KCAP);
    const int n2 = min(s_cnt[tid + 512], KCAP);
    const int n3 = min(s_cnt[tid + 768], KCAP);
    const int nmax = max(max(n0, n1), max(n2, n3));

    // Output spatial offsets for this thread's 4 cells (coalesced per warp)
    const int g0 = ((ty0 + (tid >> 5)) << 9) + tx0 + (tid & 31);
    const int g1 = g0 + 8 * SS_W;
    const int g2 = g1 + 8 * SS_W;
    const int g3 = g2 + 8 * SS_W;

    const bool interior = (tx0 >= HALO) && (tx0 + TS + HALO <= SS_W) &&
                          (ty0 >= HALO) && (ty0 + TS + HALO <= SS_H);
    const int rbase = ((ty0 - HALO) << 9) + (tx0 - HALO);

    const float* imgb = img + (size_t)b * SS_CHW;
    float*       outb = out + (size_t)b * SS_CHW;

    // -------- Phase B: 16 passes of 4 channels --------
    for (int c4 = 0; c4 < SS_C; c4 += 4) {
        const float* ic0 = imgb + (size_t)c4 * SS_HW;
        const float* ic1 = ic0 + SS_HW;
        const float* ic2 = ic1 + SS_HW;
        const float* ic3 = ic2 + SS_HW;

        if (interior) {
            #pragma unroll
            for (int it = 0; it < RN / 256; it++) {
                int i  = tid + it * 256;
                int ly = i / RW, lx = i - ly * RW;
                int g  = rbase + (ly << 9) + lx;
                s_img[i] = make_float4(ic0[g], ic1[g], ic2[g], ic3[g]);
            }
        } else {
            #pragma unroll
            for (int it = 0; it < RN / 256; it++) {
                int i  = tid + it * 256;
                int ly = i / RW, lx = i - ly * RW;
                int gy = ty0 - HALO + ly, gx = tx0 - HALO + lx;
                float4 v = make_float4(0.f, 0.f, 0.f, 0.f);
                if ((unsigned)gx < SS_W && (unsigned)gy < SS_H) {
                    int g = (gy << 9) + gx;
                    v = make_float4(ic0[g], ic1[g], ic2[g], ic3[g]);
                }
                s_img[i] = v;
            }
        }
        __syncthreads();

        float4 A0 = make_float4(0.f, 0.f, 0.f, 0.f);
        float4 A1 = A0, A2 = A0, A3 = A0;

        // Interleaved over the 4 owned cells: up to 8 LDS in flight/iteration.
        for (int i = 0; i < nmax; i++) {
            const unsigned* row = s_bin + i * NCELLS;
            if (i < n0) {
                unsigned e = row[tid];
                float w = (float)(e >> 12) * W_INV;
                float4 v = s_img[e & 0xFFFu];
                A0.x += w * v.x; A0.y += w * v.y; A0.z += w * v.z; A0.w += w * v.w;
            }
            if (i < n1) {
                unsigned e = row[tid + 256];
                float w = (float)(e >> 12) * W_INV;
                float4 v = s_img[e & 0xFFFu];
                A1.x += w * v.x; A1.y += w * v.y; A1.z += w * v.z; A1.w += w * v.w;
            }
            if (i < n2) {
                unsigned e = row[tid + 512];
                float w = (float)(e >> 12) * W_INV;
                float4 v = s_img[e & 0xFFFu];
                A2.x += w * v.x; A2.y += w * v.y; A2.z += w * v.z; A2.w += w * v.w;
            }
            if (i < n3) {
                unsigned e = row[tid + 768];
                float w = (float)(e >> 12) * W_INV;
                float4 v = s_img[e & 0xFFFu];
                A3.x += w * v.x; A3.y += w * v.y; A3.z += w * v.z; A3.w += w * v.w;
            }
        }

        float* o0 = outb + (size_t)c4 * SS_HW;
        float* o1 = o0 + SS_HW;
        float* o2 = o1 + SS_HW;
        float* o3 = o2 + SS_HW;
        __stcs(o0 + g0, A0.x); __stcs(o1 + g0, A0.y); __stcs(o2 + g0, A0.z); __stcs(o3 + g0, A0.w);
        __stcs(o0 + g1, A1.x); __stcs(o1 + g1, A1.y); __stcs(o2 + g1, A1.z); __stcs(o3 + g1, A1.w);
        __stcs(o0 + g2, A2.x); __stcs(o1 + g2, A2.y); __stcs(o2 + g2, A2.z); __stcs(o3 + g2, A2.w);
        __stcs(o0 + g3, A3.x); __stcs(o1 + g3, A3.y); __stcs(o2 + g3, A3.z); __stcs(o3 + g3, A3.w);
        __syncthreads();
    }
}

// ---------------------------------------------------------------------------
// Overflow splat: rare contributions, global atomics, all 64 channels.
// ---------------------------------------------------------------------------
__global__ __launch_bounds__(256) void ss_ovf_kernel(
    const float* __restrict__ img, float* __restrict__ out)
{
    int n = g_ovf_n;
    if (n > OVF_CAP) n = OVF_CAP;
    long long total = (long long)n * SS_C;
    long long stride = (long long)gridDim.x * blockDim.x;
    for (long long i = blockIdx.x * (long long)blockDim.x + threadIdx.x;
         i < total; i += stride) {
        int e  = (int)(i >> 6);        // / 64
        int c  = (int)(i & 63);
        int cellp = g_ovf_cell[e];
        int bb    = (cellp >> 18) & 3;
        int sp    = cellp & (SS_HW - 1);
        int ssp   = g_ovf_src[e] & (SS_HW - 1);
        size_t plane = (size_t)bb * SS_CHW + (size_t)c * SS_HW;
        atomicAdd(out + plane + sp, img[plane + ssp] * g_ovf_w[e]);
    }
}

// ---------------------------------------------------------------------------
extern "C" void kernel_launch(void* const* d_in, const int* in_sizes, int n_in,
                              void* d_out, int out_size) {
    const float* img  = (const float*)d_in[0];
    const float* flow = (const float*)d_in[1];
    float* out = (float*)d_out;

    cudaFuncSetAttribute(ss_gather_kernel,
                         cudaFuncAttributeMaxDynamicSharedMemorySize, SMEM_BYTES);

    // g_ovf_n starts at 0 (static init); reset at the END re-arms it for the
    // next invocation, keeping every call identical (graph-safe).
    ss_gather_kernel<<<SS_B * 16 * 16, 256, SMEM_BYTES>>>(img, flow, out);
    ss_ovf_kernel<<<512, 256>>>(img, out);
    ss_reset_kernel<<<1, 1>>>();
}

// round 12
// speedup vs baseline: 1.2697x; 1.2697x over previous
#include <cuda_runtime.h>

// ModuleSoftsplat forward summation splatting, tiled-gather v5.
// image [4,64,512,512] f32, flow [4,2,512,512] f32 -> out [4,64,512,512] f32.
//
// v5 vs v3 (297us gather): 8 channels per pass (8 passes, not 16), packed
// 4-byte bin entries whose weight decodes with a single AND (float bits
// rounded to 20 high bits, low 12 bits = smem index). KCAP=9. Same smem
// footprint as v3 (114,688 B -> 2 CTAs/SM).

#define SS_B   4
#define SS_C   64
#define SS_H   512
#define SS_W   512
#define SS_HW  (SS_H * SS_W)
#define SS_CHW (SS_C * SS_HW)

#define TS     32
#define HALO   8
#define RW     (TS + 2 * HALO)        // 48
#define RN     (RW * RW)              // 2304
#define KCAP   9
#define NCELLS (TS * TS)              // 1024

#define OVF_CAP (4 * SS_B * SS_HW)

// smem: cnt 4096 + bin 36864 + img 2*36864 = 114688 bytes -> 2 CTAs/SM
#define SM_BIN_OFF  (NCELLS * 4)
#define SM_IMG0_OFF (SM_BIN_OFF + NCELLS * KCAP * 4)
#define SM_IMG1_OFF (SM_IMG0_OFF + RN * 16)
#define SMEM_BYTES  (SM_IMG1_OFF + RN * 16)

__device__ int   g_ovf_n;
__device__ int   g_ovf_cell[OVF_CAP];   // (b<<18) | (y<<9) | x
__device__ int   g_ovf_src [OVF_CAP];   // (b<<18) | spatial
__device__ float g_ovf_w   [OVF_CAP];

__device__ __forceinline__ void ovf_append(int cellp, int src, float w) {
    int slot = atomicAdd(&g_ovf_n, 1);
    if (slot < OVF_CAP) {
        g_ovf_cell[slot] = cellp;
        g_ovf_src [slot] = src;
        g_ovf_w   [slot] = w;
    }
}

__global__ void ss_reset_kernel() { g_ovf_n = 0; }

// Pack: round weight's float bits to 20 high bits, OR in 12-bit smem index.
__device__ __forceinline__ unsigned pack_entry(float w, int sidx) {
    unsigned b = __float_as_uint(w);
    b = (b + 0x800u) & 0xFFFFF000u;     // round-to-nearest on low 12 mantissa bits
    return b | (unsigned)sidx;
}

// ---------------------------------------------------------------------------
// Main tiled gather kernel. Grid: 1024 = b(2) | ty(4) | tx(4).
// ---------------------------------------------------------------------------
__global__ __launch_bounds__(256, 2) void ss_gather_kernel(
    const float* __restrict__ img,
    const float* __restrict__ flow,
    float* __restrict__ out)
{
    extern __shared__ unsigned char sraw[];
    int*      s_cnt  = (int*)sraw;
    unsigned* s_bin  = (unsigned*)(sraw + SM_BIN_OFF);   // [cell][slot], KCAP=9
    float4*   s_img0 = (float4*)(sraw + SM_IMG0_OFF);    // channels c..c+3
    float4*   s_img1 = (float4*)(sraw + SM_IMG1_OFF);    // channels c+4..c+7

    const int tid = threadIdx.x;
    const int bi  = blockIdx.x;
    const int tx0 = (bi & 15) * TS;
    const int ty0 = ((bi >> 4) & 15) * TS;
    const int b   = bi >> 8;

    for (int i = tid; i < NCELLS; i += 256) s_cnt[i] = 0;
    __syncthreads();

    // -------- Phase A: bin contributors (channel-independent, once) --------
    const float* flowb = flow + (size_t)b * 2 * SS_HW;
    #pragma unroll
    for (int it = 0; it < RN / 256; it++) {
        int i  = tid + it * 256;
        int ly = i / RW, lx = i - ly * RW;
        int gy = ty0 - HALO + ly, gx = tx0 - HALO + lx;
        if ((unsigned)gx >= SS_W || (unsigned)gy >= SS_H) continue;
        int sp = (gy << 9) + gx;
        float fx = flowb[sp]         + (float)gx;
        float fy = flowb[sp + SS_HW] + (float)gy;
        float x0f = floorf(fx), y0f = floorf(fy);
        int x0 = (int)x0f, y0 = (int)y0f;
        float wx1 = fx - x0f, wx0 = 1.0f - wx1;
        float wy1 = fy - y0f, wy0 = 1.0f - wy1;
        int sidx = ly * RW + lx;
        bool own = (gx >= tx0) && (gx < tx0 + TS) && (gy >= ty0) && (gy < ty0 + TS);
        #pragma unroll
        for (int k = 0; k < 4; k++) {
            int dx = k & 1, dy = k >> 1;
            int cx = x0 + dx, cy = y0 + dy;
            if ((unsigned)cx >= SS_W || (unsigned)cy >= SS_H) continue;
            float w = (dx ? wx1 : wx0) * (dy ? wy1 : wy0);
            int lcx = cx - tx0, lcy = cy - ty0;
            if ((unsigned)lcx < TS && (unsigned)lcy < TS) {
                int cid  = (lcy << 5) + lcx;
                int slot = atomicAdd(&s_cnt[cid], 1);
                if (slot < KCAP)
                    s_bin[cid * KCAP + slot] = pack_entry(w, sidx);
                else
                    ovf_append((b << 18) | (cy << 9) | cx, (b << 18) | sp, w);
            } else if (own) {
                int tcx = cx & ~(TS - 1), tcy = cy & ~(TS - 1);
                bool cap = (gx >= tcx - HALO) && (gx < tcx + TS + HALO) &&
                           (gy >= tcy - HALO) && (gy < tcy + TS + HALO);
                if (!cap)
                    ovf_append((b << 18) | (cy << 9) | cx, (b << 18) | sp, w);
            }
        }
    }
    __syncthreads();

    const int n0 = min(s_cnt[tid      ], KCAP);
    const int n1 = min(s_cnt[tid + 256], KCAP);
    const int n2 = min(s_cnt[tid + 512], KCAP);
    const int n3 = min(s_cnt[tid + 768], KCAP);
    const int nmax = max(max(n0, n1), max(n2, n3));

    const unsigned* bp0 = s_bin + (tid      ) * KCAP;
    const unsigned* bp1 = s_bin + (tid + 256) * KCAP;
    const unsigned* bp2 = s_bin + (tid + 512) * KCAP;
    const unsigned* bp3 = s_bin + (tid + 768) * KCAP;

    const int g0 = ((ty0 + (tid >> 5)) << 9) + tx0 + (tid & 31);
    const int g1 = g0 + 8 * SS_W;
    const int g2 = g1 + 8 * SS_W;
    const int g3 = g2 + 8 * SS_W;

    const bool interior = (tx0 >= HALO) && (tx0 + TS + HALO <= SS_W) &&
                          (ty0 >= HALO) && (ty0 + TS + HALO <= SS_H);
    const int rbase = ((ty0 - HALO) << 9) + (tx0 - HALO);

    const float* imgb = img + (size_t)b * SS_CHW;
    float*       outb = out + (size_t)b * SS_CHW;

    // -------- Phase B: 8 passes of 8 channels --------
    for (int c8 = 0; c8 < SS_C; c8 += 8) {
        const float* ic = imgb + (size_t)c8 * SS_HW;

        if (interior) {
            #pragma unroll
            for (int it = 0; it < RN / 256; it++) {
                int i  = tid + it * 256;
                int ly = i / RW, lx = i - ly * RW;
                int g  = rbase + (ly << 9) + lx;
                s_img0[i] = make_float4(ic[g],
                                        ic[g + 1 * SS_HW],
                                        ic[g + 2 * SS_HW],
                                        ic[g + 3 * SS_HW]);
                s_img1[i] = make_float4(ic[g + 4 * SS_HW],
                                        ic[g + 5 * SS_HW],
                                        ic[g + 6 * SS_HW],
                                        ic[g + 7 * SS_HW]);
            }
        } else {
            #pragma unroll
            for (int it = 0; it < RN / 256; it++) {
                int i  = tid + it * 256;
                int ly = i / RW, lx = i - ly * RW;
                int gy = ty0 - HALO + ly, gx = tx0 - HALO + lx;
                float4 v0 = make_float4(0.f, 0.f, 0.f, 0.f);
                float4 v1 = v0;
                if ((unsigned)gx < SS_W && (unsigned)gy < SS_H) {
                    int g = (gy << 9) + gx;
                    v0 = make_float4(ic[g],
                                     ic[g + 1 * SS_HW],
                                     ic[g + 2 * SS_HW],
                                     ic[g + 3 * SS_HW]);
                    v1 = make_float4(ic[g + 4 * SS_HW],
                                     ic[g + 5 * SS_HW],
                                     ic[g + 6 * SS_HW],
                                     ic[g + 7 * SS_HW]);
                }
                s_img0[i] = v0;
                s_img1[i] = v1;
            }
        }
        __syncthreads();

        float4 A0a = make_float4(0.f, 0.f, 0.f, 0.f), A0b = A0a;
        float4 A1a = A0a, A1b = A0a;
        float4 A2a = A0a, A2b = A0a;
        float4 A3a = A0a, A3b = A0a;

        for (int i = 0; i < nmax; i++) {
            if (i < n0) {
                unsigned e = bp0[i];
                float w = __uint_as_float(e & 0xFFFFF000u);
                unsigned s = e & 0xFFFu;
                float4 v0 = s_img0[s], v1 = s_img1[s];
                A0a.x += w * v0.x; A0a.y += w * v0.y; A0a.z += w * v0.z; A0a.w += w * v0.w;
                A0b.x += w * v1.x; A0b.y += w * v1.y; A0b.z += w * v1.z; A0b.w += w * v1.w;
            }
            if (i < n1) {
                unsigned e = bp1[i];
                float w = __uint_as_float(e & 0xFFFFF000u);
                unsigned s = e & 0xFFFu;
                float4 v0 = s_img0[s], v1 = s_img1[s];
                A1a.x += w * v0.x; A1a.y += w * v0.y; A1a.z += w * v0.z; A1a.w += w * v0.w;
                A1b.x += w * v1.x; A1b.y += w * v1.y; A1b.z += w * v1.z; A1b.w += w * v1.w;
            }
            if (i < n2) {
                unsigned e = bp2[i];
                float w = __uint_as_float(e & 0xFFFFF000u);
                unsigned s = e & 0xFFFu;
                float4 v0 = s_img0[s], v1 = s_img1[s];
                A2a.x += w * v0.x; A2a.y += w * v0.y; A2a.z += w * v0.z; A2a.w += w * v0.w;
                A2b.x += w * v1.x; A2b.y += w * v1.y; A2b.z += w * v1.z; A2b.w += w * v1.w;
            }
            if (i < n3) {
                unsigned e = bp3[i];
                float w = __uint_as_float(e & 0xFFFFF000u);
                unsigned s = e & 0xFFFu;
                float4 v0 = s_img0[s], v1 = s_img1[s];
                A3a.x += w * v0.x; A3a.y += w * v0.y; A3a.z += w * v0.z; A3a.w += w * v0.w;
                A3b.x += w * v1.x; A3b.y += w * v1.y; A3b.z += w * v1.z; A3b.w += w * v1.w;
            }
        }

        float* o = outb + (size_t)c8 * SS_HW;
        __stcs(o + 0 * SS_HW + g0, A0a.x); __stcs(o + 1 * SS_HW + g0, A0a.y);
        __stcs(o + 2 * SS_HW + g0, A0a.z); __stcs(o + 3 * SS_HW + g0, A0a.w);
        __stcs(o + 4 * SS_HW + g0, A0b.x); __stcs(o + 5 * SS_HW + g0, A0b.y);
        __stcs(o + 6 * SS_HW + g0, A0b.z); __stcs(o + 7 * SS_HW + g0, A0b.w);

        __stcs(o + 0 * SS_HW + g1, A1a.x); __stcs(o + 1 * SS_HW + g1, A1a.y);
        __stcs(o + 2 * SS_HW + g1, A1a.z); __stcs(o + 3 * SS_HW + g1, A1a.w);
        __stcs(o + 4 * SS_HW + g1, A1b.x); __stcs(o + 5 * SS_HW + g1, A1b.y);
        __stcs(o + 6 * SS_HW + g1, A1b.z); __stcs(o + 7 * SS_HW + g1, A1b.w);

        __stcs(o + 0 * SS_HW + g2, A2a.x); __stcs(o + 1 * SS_HW + g2, A2a.y);
        __stcs(o + 2 * SS_HW + g2, A2a.z); __stcs(o + 3 * SS_HW + g2, A2a.w);
        __stcs(o + 4 * SS_HW + g2, A2b.x); __stcs(o + 5 * SS_HW + g2, A2b.y);
        __stcs(o + 6 * SS_HW + g2, A2b.z); __stcs(o + 7 * SS_HW + g2, A2b.w);

        __stcs(o + 0 * SS_HW + g3, A3a.x); __stcs(o + 1 * SS_HW + g3, A3a.y);
        __stcs(o + 2 * SS_HW + g3, A3a.z); __stcs(o + 3 * SS_HW + g3, A3a.w);
        __stcs(o + 4 * SS_HW + g3, A3b.x); __stcs(o + 5 * SS_HW + g3, A3b.y);
        __stcs(o + 6 * SS_HW + g3, A3b.z); __stcs(o + 7 * SS_HW + g3, A3b.w);
        __syncthreads();
    }
}

// ---------------------------------------------------------------------------
// Overflow splat: rare contributions, global atomics, all 64 channels.
// ---------------------------------------------------------------------------
__global__ __launch_bounds__(256) void ss_ovf_kernel(
    const float* __restrict__ img, float* __restrict__ out)
{
    int n = g_ovf_n;
    if (n > OVF_CAP) n = OVF_CAP;
    long long total = (long long)n * SS_C;
    long long stride = (long long)gridDim.x * blockDim.x;
    for (long long i = blockIdx.x * (long long)blockDim.x + threadIdx.x;
         i < total; i += stride) {
        int e  = (int)(i >> 6);
        int c  = (int)(i & 63);
        int cellp = g_ovf_cell[e];
        int bb    = (cellp >> 18) & 3;
        int sp    = cellp & (SS_HW - 1);
        int ssp   = g_ovf_src[e] & (SS_HW - 1);
        size_t plane = (size_t)bb * SS_CHW + (size_t)c * SS_HW;
        atomicAdd(out + plane + sp, img[plane + ssp] * g_ovf_w[e]);
    }
}

// ---------------------------------------------------------------------------
extern "C" void kernel_launch(void* const* d_in, const int* in_sizes, int n_in,
                              void* d_out, int out_size) {
    const float* img  = (const float*)d_in[0];
    const float* flow = (const float*)d_in[1];
    float* out = (float*)d_out;

    cudaFuncSetAttribute(ss_gather_kernel,
                         cudaFuncAttributeMaxDynamicSharedMemorySize, SMEM_BYTES);

    ss_gather_kernel<<<SS_B * 16 * 16, 256, SMEM_BYTES>>>(img, flow, out);
    ss_ovf_kernel<<<512, 256>>>(img, out);
    ss_reset_kernel<<<1, 1>>>();
}

// round 14
// speedup vs baseline: 2.0534x; 1.6172x over previous
#include <cuda_runtime.h>
#include <cuda.h>

// ModuleSoftsplat forward summation splatting, tiled-gather v6 (TMA pipeline).
// image [4,64,512,512] f32, flow [4,2,512,512] f32 -> out [4,64,512,512] f32.
//
// v6 vs v5 (297us gather): image halo staging via TMA 2D tile loads into two
// planar 4-channel smem buffers, double-buffered with mbarriers so the fill of
// pass p+1/p+2 overlaps the gather of pass p. Per-thread staging instructions
// (~580 LDG/STS) are removed from the issue stream; TMA OOB zero-fill removes
// the border special-case. Bins (KCAP=9, packed 4B entries) unchanged.

#define SS_B   4
#define SS_C   64
#define SS_H   512
#define SS_W   512
#define SS_HW  (SS_H * SS_W)
#define SS_CHW (SS_C * SS_HW)

#define TS     32
#define HALO   8
#define RW     (TS + 2 * HALO)        // 48
#define RN     (RW * RW)              // 2304
#define KCAP   9
#define NCELLS (TS * TS)              // 1024
#define NPASS  16                     // 16 passes x 4 channels
#define CPB    4                      // channels per buffer/pass
#define BUFB   (CPB * RN * 4)         // 36864 bytes per buffer

#define OVF_CAP (4 * SS_B * SS_HW)

// smem layout (128B aligned blocks):
//   [0,128)      2 mbarriers
//   [128,4224)   s_cnt (1024 ints)
//   [4224,41088) s_bin (1024*9*4)
//   [41088,...)  img buf0, buf1 (planar: [ch][48][48] floats)
#define SM_MBAR_OFF 0
#define SM_CNT_OFF  128
#define SM_BIN_OFF  (SM_CNT_OFF + NCELLS * 4)
#define SM_IMG0_OFF (SM_BIN_OFF + NCELLS * KCAP * 4)
#define SM_IMG1_OFF (SM_IMG0_OFF + BUFB)
#define SMEM_BYTES  (SM_IMG1_OFF + BUFB)

__device__ int   g_ovf_n;
__device__ int   g_ovf_cell[OVF_CAP];   // (b<<18) | (y<<9) | x
__device__ int   g_ovf_src [OVF_CAP];   // (b<<18) | spatial
__device__ float g_ovf_w   [OVF_CAP];

__device__ __forceinline__ void ovf_append(int cellp, int src, float w) {
    int slot = atomicAdd(&g_ovf_n, 1);
    if (slot < OVF_CAP) {
        g_ovf_cell[slot] = cellp;
        g_ovf_src [slot] = src;
        g_ovf_w   [slot] = w;
    }
}

__global__ void ss_reset_kernel() { g_ovf_n = 0; }

// Pack: round weight's float bits to 20 high bits, OR in 12-bit smem index.
__device__ __forceinline__ unsigned pack_entry(float w, int sidx) {
    unsigned b = __float_as_uint(w);
    b = (b + 0x800u) & 0xFFFFF000u;
    return b | (unsigned)sidx;
}

__device__ __forceinline__ unsigned smem_u32(const void* p) {
    unsigned a;
    asm("{ .reg .u64 t; cvta.to.shared.u64 t, %1; cvt.u32.u64 %0, t; }"
        : "=r"(a) : "l"(p));
    return a;
}

__device__ __forceinline__ void mbar_init(unsigned addr, unsigned count) {
    asm volatile("mbarrier.init.shared.b64 [%0], %1;" :: "r"(addr), "r"(count) : "memory");
}
__device__ __forceinline__ void mbar_expect_tx(unsigned addr, unsigned bytes) {
    asm volatile("mbarrier.arrive.expect_tx.shared.b64 _, [%0], %1;"
                 :: "r"(addr), "r"(bytes) : "memory");
}
__device__ __forceinline__ void mbar_wait(unsigned addr, unsigned parity) {
    asm volatile(
        "{\n\t.reg .pred P;\n"
        "WLP%=:\n\t"
        "mbarrier.try_wait.parity.acquire.cta.shared::cta.b64 P, [%0], %1, 0x989680;\n\t"
        "@P bra WDN%=;\n\t"
        "bra WLP%=;\n"
        "WDN%=:\n\t}"
        :: "r"(addr), "r"(parity) : "memory");
}
__device__ __forceinline__ void tma_load3d(unsigned dst, const CUtensorMap* m,
                                           int x, int y, int z, unsigned mbar) {
    asm volatile(
        "cp.async.bulk.tensor.3d.shared::cta.global.tile.mbarrier::complete_tx::bytes "
        "[%0], [%1, {%2, %3, %4}], [%5];"
        :: "r"(dst), "l"(m), "r"(x), "r"(y), "r"(z), "r"(mbar) : "memory");
}

// ---------------------------------------------------------------------------
// Main tiled gather kernel. Grid: 1024 = b(2) | ty(4) | tx(4).
// ---------------------------------------------------------------------------
__global__ __launch_bounds__(256, 2) void ss_gather_kernel(
    const __grid_constant__ CUtensorMap tmap,
    const float* __restrict__ img,
    const float* __restrict__ flow,
    float* __restrict__ out,
    int use_tma)
{
    extern __shared__ unsigned char sraw[];
    int*      s_cnt = (int*)(sraw + SM_CNT_OFF);
    unsigned* s_bin = (unsigned*)(sraw + SM_BIN_OFF);   // [cell][slot]
    float*    s_buf[2] = { (float*)(sraw + SM_IMG0_OFF), (float*)(sraw + SM_IMG1_OFF) };

    const int tid = threadIdx.x;
    const int bi  = blockIdx.x;
    const int tx0 = (bi & 15) * TS;
    const int ty0 = ((bi >> 4) & 15) * TS;
    const int b   = bi >> 8;

    const unsigned mbar0 = smem_u32(sraw + SM_MBAR_OFF);
    const unsigned mbar1 = mbar0 + 8;
    const unsigned buf0u = smem_u32(sraw + SM_IMG0_OFF);
    const unsigned buf1u = smem_u32(sraw + SM_IMG1_OFF);

    // Kick off fills for passes 0 and 1 before binning (overlap).
    if (use_tma && tid == 0) {
        mbar_init(mbar0, 1);
        mbar_init(mbar1, 1);
        asm volatile("fence.proxy.async.shared::cta;" ::: "memory");
        mbar_expect_tx(mbar0, BUFB);
        #pragma unroll
        for (int j = 0; j < CPB; j++)
            tma_load3d(buf0u + j * (RN * 4), &tmap,
                       tx0 - HALO, ty0 - HALO, b * SS_C + j, mbar0);
        mbar_expect_tx(mbar1, BUFB);
        #pragma unroll
        for (int j = 0; j < CPB; j++)
            tma_load3d(buf1u + j * (RN * 4), &tmap,
                       tx0 - HALO, ty0 - HALO, b * SS_C + CPB + j, mbar1);
    }

    for (int i = tid; i < NCELLS; i += 256) s_cnt[i] = 0;
    __syncthreads();

    // -------- Phase A: bin contributors (channel-independent, once) --------
    const float* flowb = flow + (size_t)b * 2 * SS_HW;
    #pragma unroll
    for (int it = 0; it < RN / 256; it++) {
        int i  = tid + it * 256;
        int ly = i / RW, lx = i - ly * RW;
        int gy = ty0 - HALO + ly, gx = tx0 - HALO + lx;
        if ((unsigned)gx >= SS_W || (unsigned)gy >= SS_H) continue;
        int sp = (gy << 9) + gx;
        float fx = flowb[sp]         + (float)gx;
        float fy = flowb[sp + SS_HW] + (float)gy;
        float x0f = floorf(fx), y0f = floorf(fy);
        int x0 = (int)x0f, y0 = (int)y0f;
        float wx1 = fx - x0f, wx0 = 1.0f - wx1;
        float wy1 = fy - y0f, wy0 = 1.0f - wy1;
        int sidx = ly * RW + lx;
        bool own = (gx >= tx0) && (gx < tx0 + TS) && (gy >= ty0) && (gy < ty0 + TS);
        #pragma unroll
        for (int k = 0; k < 4; k++) {
            int dx = k & 1, dy = k >> 1;
            int cx = x0 + dx, cy = y0 + dy;
            if ((unsigned)cx >= SS_W || (unsigned)cy >= SS_H) continue;
            float w = (dx ? wx1 : wx0) * (dy ? wy1 : wy0);
            int lcx = cx - tx0, lcy = cy - ty0;
            if ((unsigned)lcx < TS && (unsigned)lcy < TS) {
                int cid  = (lcy << 5) + lcx;
                int slot = atomicAdd(&s_cnt[cid], 1);
                if (slot < KCAP)
                    s_bin[cid * KCAP + slot] = pack_entry(w, sidx);
                else
                    ovf_append((b << 18) | (cy << 9) | cx, (b << 18) | sp, w);
            } else if (own) {
                int tcx = cx & ~(TS - 1), tcy = cy & ~(TS - 1);
                bool cap = (gx >= tcx - HALO) && (gx < tcx + TS + HALO) &&
                           (gy >= tcy - HALO) && (gy < tcy + TS + HALO);
                if (!cap)
                    ovf_append((b << 18) | (cy << 9) | cx, (b << 18) | sp, w);
            }
        }
    }
    __syncthreads();

    const int n0 = min(s_cnt[tid      ], KCAP);
    const int n1 = min(s_cnt[tid + 256], KCAP);
    const int n2 = min(s_cnt[tid + 512], KCAP);
    const int n3 = min(s_cnt[tid + 768], KCAP);
    const int nmax = max(max(n0, n1), max(n2, n3));

    const unsigned* bp0 = s_bin + (tid      ) * KCAP;
    const unsigned* bp1 = s_bin + (tid + 256) * KCAP;
    const unsigned* bp2 = s_bin + (tid + 512) * KCAP;
    const unsigned* bp3 = s_bin + (tid + 768) * KCAP;

    const int g0 = ((ty0 + (tid >> 5)) << 9) + tx0 + (tid & 31);
    const int g1 = g0 + 8 * SS_W;
    const int g2 = g1 + 8 * SS_W;
    const int g3 = g2 + 8 * SS_W;

    float* outb = out + (size_t)b * SS_CHW;

    // -------- Phase B: 16 passes of 4 channels, double-buffered --------
    for (int p = 0; p < NPASS; p++) {
        const int s = p & 1;
        const float* sb = s_buf[s];

        if (use_tma) {
            mbar_wait(s ? mbar1 : mbar0, (p >> 1) & 1);
        } else {
            // Fallback staging via LDG (planar layout).
            const float* ic = img + (size_t)b * SS_CHW + (size_t)(p * CPB) * SS_HW;
            float* wbuf = s_buf[s];
            #pragma unroll
            for (int it = 0; it < RN / 256; it++) {
                int i  = tid + it * 256;
                int ly = i / RW, lx = i - ly * RW;
                int gy = ty0 - HALO + ly, gx = tx0 - HALO + lx;
                float v0 = 0.f, v1 = 0.f, v2 = 0.f, v3 = 0.f;
                if ((unsigned)gx < SS_W && (unsigned)gy < SS_H) {
                    int g = (gy << 9) + gx;
                    v0 = ic[g];
                    v1 = ic[g + 1 * SS_HW];
                    v2 = ic[g + 2 * SS_HW];
                    v3 = ic[g + 3 * SS_HW];
                }
                wbuf[i] = v0;
                wbuf[i + RN] = v1;
                wbuf[i + 2 * RN] = v2;
                wbuf[i + 3 * RN] = v3;
            }
            __syncthreads();
        }

        float4 A0 = make_float4(0.f, 0.f, 0.f, 0.f);
        float4 A1 = A0, A2 = A0, A3 = A0;

        for (int i = 0; i < nmax; i++) {
            if (i < n0) {
                unsigned e = bp0[i];
                float w = __uint_as_float(e & 0xFFFFF000u);
                const float* q = sb + (e & 0xFFFu);
                A0.x += w * q[0];      A0.y += w * q[RN];
                A0.z += w * q[2 * RN]; A0.w += w * q[3 * RN];
            }
            if (i < n1) {
                unsigned e = bp1[i];
                float w = __uint_as_float(e & 0xFFFFF000u);
                const float* q = sb + (e & 0xFFFu);
                A1.x += w * q[0];      A1.y += w * q[RN];
                A1.z += w * q[2 * RN]; A1.w += w * q[3 * RN];
            }
            if (i < n2) {
                unsigned e = bp2[i];
                float w = __uint_as_float(e & 0xFFFFF000u);
                const float* q = sb + (e & 0xFFFu);
                A2.x += w * q[0];      A2.y += w * q[RN];
                A2.z += w * q[2 * RN]; A2.w += w * q[3 * RN];
            }
            if (i < n3) {
                unsigned e = bp3[i];
                float w = __uint_as_float(e & 0xFFFFF000u);
                const float* q = sb + (e & 0xFFFu);
                A3.x += w * q[0];      A3.y += w * q[RN];
                A3.z += w * q[2 * RN]; A3.w += w * q[3 * RN];
            }
        }

        float* o = outb + (size_t)(p * CPB) * SS_HW;
        __stcs(o + g0, A0.x); __stcs(o + SS_HW + g0, A0.y);
        __stcs(o + 2 * SS_HW + g0, A0.z); __stcs(o + 3 * SS_HW + g0, A0.w);
        __stcs(o + g1, A1.x); __stcs(o + SS_HW + g1, A1.y);
        __stcs(o + 2 * SS_HW + g1, A1.z); __stcs(o + 3 * SS_HW + g1, A1.w);
        __stcs(o + g2, A2.x); __stcs(o + SS_HW + g2, A2.y);
        __stcs(o + 2 * SS_HW + g2, A2.z); __stcs(o + 3 * SS_HW + g2, A2.w);
        __stcs(o + g3, A3.x); __stcs(o + SS_HW + g3, A3.y);
        __stcs(o + 2 * SS_HW + g3, A3.z); __stcs(o + 3 * SS_HW + g3, A3.w);

        __syncthreads();   // all reads of buf[s] done before refill

        if (use_tma && p + 2 < NPASS && tid == 0) {
            unsigned mb = s ? mbar1 : mbar0;
            unsigned bu = s ? buf1u : buf0u;
            mbar_expect_tx(mb, BUFB);
            #pragma unroll
            for (int j = 0; j < CPB; j++)
                tma_load3d(bu + j * (RN * 4), &tmap,
                           tx0 - HALO, ty0 - HALO,
                           b * SS_C + (p + 2) * CPB + j, mb);
        }
    }
}

// ---------------------------------------------------------------------------
// Overflow splat: rare contributions, global atomics, all 64 channels.
// ---------------------------------------------------------------------------
__global__ __launch_bounds__(256) void ss_ovf_kernel(
    const float* __restrict__ img, float* __restrict__ out)
{
    int n = g_ovf_n;
    if (n > OVF_CAP) n = OVF_CAP;
    long long total = (long long)n * SS_C;
    long long stride = (long long)gridDim.x * blockDim.x;
    for (long long i = blockIdx.x * (long long)blockDim.x + threadIdx.x;
         i < total; i += stride) {
        int e  = (int)(i >> 6);
        int c  = (int)(i & 63);
        int cellp = g_ovf_cell[e];
        int bb    = (cellp >> 18) & 3;
        int sp    = cellp & (SS_HW - 1);
        int ssp   = g_ovf_src[e] & (SS_HW - 1);
        size_t plane = (size_t)bb * SS_CHW + (size_t)c * SS_HW;
        atomicAdd(out + plane + sp, img[plane + ssp] * g_ovf_w[e]);
    }
}

// ---------------------------------------------------------------------------
typedef CUresult (*EncodeTiledFn)(
    CUtensorMap*, CUtensorMapDataType, cuuint32_t, void*,
    const cuuint64_t*, const cuuint64_t*, const cuuint32_t*, const cuuint32_t*,
    CUtensorMapInterleave, CUtensorMapSwizzle, CUtensorMapL2promotion,
    CUtensorMapFloatOOBfill);

extern "C" void kernel_launch(void* const* d_in, const int* in_sizes, int n_in,
                              void* d_out, int out_size) {
    const float* img  = (const float*)d_in[0];
    const float* flow = (const float*)d_in[1];
    float* out = (float*)d_out;

    // Build tensormap: image as 3D (x=512 f32, y=512, z=256 planes), box 48x48x1.
    CUtensorMap tmap;
    memset(&tmap, 0, sizeof(tmap));
    int use_tma = 0;
    void* fp = nullptr;
    cudaDriverEntryPointQueryResult qres = cudaDriverEntryPointSymbolNotFound;
#if CUDART_VERSION >= 12050
    cudaGetDriverEntryPointByVersion("cuTensorMapEncodeTiled", &fp, 12000,
                                     cudaEnableDefault, &qres);
#else
    cudaGetDriverEntryPoint("cuTensorMapEncodeTiled", &fp,
                            cudaEnableDefault, &qres);
#endif
    if (fp && qres == cudaDriverEntryPointSuccess) {
        cuuint64_t dims[3]    = { SS_W, SS_H, SS_B * SS_C };
        cuuint64_t strides[2] = { SS_W * 4ull, (cuuint64_t)SS_HW * 4ull };
        cuuint32_t box[3]     = { RW, RW, 1 };
        cuuint32_t estr[3]    = { 1, 1, 1 };
        CUresult r = ((EncodeTiledFn)fp)(
            &tmap, CU_TENSOR_MAP_DATA_TYPE_FLOAT32, 3, (void*)img,
            dims, strides, box, estr,
            CU_TENSOR_MAP_INTERLEAVE_NONE, CU_TENSOR_MAP_SWIZZLE_NONE,
            CU_TENSOR_MAP_L2_PROMOTION_L2_128B,
            CU_TENSOR_MAP_FLOAT_OOB_FILL_NONE);
        if (r == CUDA_SUCCESS) use_tma = 1;
    }

    cudaFuncSetAttribute(ss_gather_kernel,
                         cudaFuncAttributeMaxDynamicSharedMemorySize, SMEM_BYTES);

    ss_gather_kernel<<<SS_B * 16 * 16, 256, SMEM_BYTES>>>(tmap, img, flow, out, use_tma);
    ss_ovf_kernel<<<512, 256>>>(img, out);
    ss_reset_kernel<<<1, 1>>>();
}